// round 10
// baseline (speedup 1.0000x reference)
#include <cuda_runtime.h>
#include <cuda_fp16.h>
#include <math.h>
#include <stdint.h>

#define Bn 32
#define Tn 512
#define Un 64
#define Vn 32000
#define Hn 512
#define En 512
#define HEn 1024
#define G3H 1536
#define NB 128
#define BH (Bn * Hn)

#define SMEM_W_BYTES   52224
#define SMEM_X_BYTES   34816
#define SMEM_SCR_BYTES 16384
#define SMEM_TOTAL_B   (SMEM_W_BYTES + SMEM_X_BYTES + SMEM_SCR_BYTES)

#define GEMM_SMEM_B    73728

// ---------------- scratch (device globals) ----------------
__device__ __half g_enc_h[(size_t)Bn * Tn * En];
__device__ __half g_encproj_h[(size_t)Bn * Tn * Hn];
__device__ __half g_Wattn_h[Hn * En];
__device__ __half g_Wih0_h[G3H * HEn];
__device__ __half g_Wih1_h[G3H * Hn];
__device__ __half g_Whh0_h[G3H * Hn];
__device__ __half g_Whh1_h[G3H * Hn];
__device__ __half g_Wout_h[(size_t)Vn * HEn];
__device__ float  g_embQ[(size_t)Un * Bn * Hn];
__device__ __half g_embH[(size_t)Un * Bn * Hn];
__device__ float  g_gi0pre[(size_t)Un * Bn * G3H];
__device__ __half g_acts[(size_t)Un * Bn * HEn];
__device__ float  g_h0buf[2 * BH], g_h1buf[2 * BH];
__device__ __half g_h0h[2 * BH], g_h1h[2 * BH];
__device__ float  g_gh0[Bn * G3H], g_gh1[Bn * G3H];
// each counter on its OWN 128B line (kills spin/atomic slice contention)
__device__ __align__(128) unsigned g_cnt_attn;
__device__ __align__(128) unsigned g_cnt_gh0;
__device__ __align__(128) unsigned g_cnt_gh1;
__device__ __align__(128) unsigned g_cnt_g0;
__device__ __align__(128) unsigned g_cnt_g1;

__device__ __forceinline__ float sigmoidf_(float x) { return 1.0f / (1.0f + expf(-x)); }

__device__ __forceinline__ void hmma(float* c, unsigned a0, unsigned a1, unsigned a2,
                                     unsigned a3, unsigned b0, unsigned b1) {
    asm volatile(
        "mma.sync.aligned.m16n8k16.row.col.f32.f16.f16.f32 "
        "{%0,%1,%2,%3},{%4,%5,%6,%7},{%8,%9},{%0,%1,%2,%3};"
        : "+f"(c[0]), "+f"(c[1]), "+f"(c[2]), "+f"(c[3])
        : "r"(a0), "r"(a1), "r"(a2), "r"(a3), "r"(b0), "r"(b1));
}

__device__ __forceinline__ void cp_async16(unsigned saddr, const void* gptr) {
    asm volatile("cp.async.cg.shared.global [%0], [%1], 16;" :: "r"(saddr), "l"(gptr));
}

#define LDSM4(d0, d1, d2, d3, addr) \
    asm volatile("ldmatrix.sync.aligned.m8n8.x4.shared.b16 {%0,%1,%2,%3}, [%4];" \
        : "=r"(d0), "=r"(d1), "=r"(d2), "=r"(d3) : "r"(addr))

// ---------------- point-to-point sync (backoff spin) ----------------
__device__ __forceinline__ void spin_until(unsigned* p, unsigned tgt) {
    if (*(volatile unsigned*)p >= tgt) return;
    while (true) {
        __nanosleep(40);
        if (*(volatile unsigned*)p >= tgt) return;
    }
}
__device__ __forceinline__ void wait1(unsigned* p, unsigned tgt) {
    if (threadIdx.x == 0) {
        spin_until(p, tgt);
        __threadfence();
    }
    __syncthreads();
}
__device__ __forceinline__ void wait2(unsigned* pa, unsigned ta, unsigned* pb, unsigned tb) {
    if (threadIdx.x == 0) {
        spin_until(pa, ta);
        spin_until(pb, tb);
        __threadfence();
    }
    __syncthreads();
}
__device__ __forceinline__ void signal(unsigned* cnt) {
    __syncthreads();
    if (threadIdx.x == 0) { __threadfence(); atomicAdd(cnt, 1u); }
}

// ---------------- mega prologue: init + embed + all f2h in ONE launch ----------------
#define N4_ENC   2097152
#define N4_WATTN 65536
#define N4_WIH0  393216
#define N4_WIH1  196608
#define N4_WHH0  196608
#define N4_WHH1  196608
#define N4_WOUT  8192000
#define N4_TOTAL (N4_ENC + N4_WATTN + N4_WIH0 + N4_WIH1 + N4_WHH0 + N4_WHH1 + N4_WOUT)

__global__ void mega_prologue(const float* __restrict__ enc, const float* __restrict__ wat,
                              const float* __restrict__ wi0, const float* __restrict__ wi1,
                              const float* __restrict__ wh0, const float* __restrict__ wh1,
                              const float* __restrict__ wo,
                              const int* __restrict__ din, const float* __restrict__ table)
{
    long long i = (long long)blockIdx.x * 256 + threadIdx.x;

    // state init
    if (i < BH) {
        g_h0buf[i] = 0.0f; g_h1buf[i] = 0.0f;
        g_h0h[i] = __float2half(0.0f); g_h1h[i] = __float2half(0.0f);
    }
    if (i == 0) {
        g_cnt_attn = 0; g_cnt_gh0 = 0; g_cnt_gh1 = 0; g_cnt_g0 = 0; g_cnt_g1 = 0;
    }

    // embedding gather (fp32 + fp16)
    if (i < Un * Bn * Hn) {
        int h = (int)i & (Hn - 1);
        int m = (int)(i >> 9);
        int u = m >> 5, b = m & 31;
        float v = table[(size_t)din[b * Un + u] * Hn + h];
        g_embQ[i] = v;
        g_embH[i] = __float2half(v);
    }

    // fp32->fp16 conversions (float4 granularity)
    if (i < N4_TOTAL) {
        const float* src; __half* dst; long long off = i;
        if (off < N4_ENC)                 { src = enc; dst = g_enc_h; }
        else if ((off -= N4_ENC)   < N4_WATTN) { src = wat; dst = g_Wattn_h; }
        else if ((off -= N4_WATTN) < N4_WIH0)  { src = wi0; dst = g_Wih0_h; }
        else if ((off -= N4_WIH0)  < N4_WIH1)  { src = wi1; dst = g_Wih1_h; }
        else if ((off -= N4_WIH1)  < N4_WHH0)  { src = wh0; dst = g_Whh0_h; }
        else if ((off -= N4_WHH0)  < N4_WHH1)  { src = wh1; dst = g_Whh1_h; }
        else { off -= N4_WHH1; src = wo; dst = g_Wout_h; }
        float4 v = reinterpret_cast<const float4*>(src)[off];
        reinterpret_cast<__half2*>(dst)[2 * off]     = __floats2half2_rn(v.x, v.y);
        reinterpret_cast<__half2*>(dst)[2 * off + 1] = __floats2half2_rn(v.z, v.w);
    }
}

// ---------------- pipelined fp16 GEMM with ldmatrix (unchanged from R9) ----------------
#define SROW 72
__global__ __launch_bounds__(256) void gemm_h16(
    const __half* __restrict__ A, const __half* __restrict__ Bw, int ldb,
    const float* __restrict__ bias, void* __restrict__ Cout,
    int M, int N, int K, int mode, int swap)
{
    extern __shared__ __align__(16) __half gsm[];
    __half* sA = gsm;
    __half* sB = gsm + 2 * 128 * SROW;

    int tid = threadIdx.x, lane = tid & 31, warp = tid >> 5;
    int wm = (warp >> 1) * 32;
    int wn = (warp & 1) * 64;
    int bm = (swap ? blockIdx.x : blockIdx.y) * 128;
    int bn = (swap ? blockIdx.y : blockIdx.x) * 128;
    int r = lane >> 2, c = (lane & 3) * 2;

    unsigned sA_u = (unsigned)__cvta_generic_to_shared(sA);
    unsigned sB_u = (unsigned)__cvta_generic_to_shared(sB);

    int ri = lane & 7, g = lane >> 3;
    unsigned laneA = (unsigned)(((ri + (g & 1) * 8) * SROW + (g >> 1) * 8) * 2);
    unsigned laneB = (unsigned)(((ri + (g >> 1) * 8) * SROW + (g & 1) * 8) * 2);

    int ldrow = tid >> 3, ldseg = (tid & 7) * 8;

    float acc[2][8][4];
#pragma unroll
    for (int mi = 0; mi < 2; mi++)
#pragma unroll
        for (int ni = 0; ni < 8; ni++)
#pragma unroll
            for (int q = 0; q < 4; q++) acc[mi][ni][q] = 0.0f;

    int nk = K >> 6;

#pragma unroll
    for (int i = 0; i < 4; i++) {
        int row = ldrow + i * 32;
        cp_async16(sA_u + (unsigned)((row * SROW + ldseg) * 2),
                   A + (size_t)(bm + row) * K + ldseg);
        cp_async16(sB_u + (unsigned)((row * SROW + ldseg) * 2),
                   Bw + (size_t)(bn + row) * ldb + ldseg);
    }
    asm volatile("cp.async.commit_group;");

    for (int ki = 0; ki < nk; ki++) {
        asm volatile("cp.async.wait_group 0;");
        __syncthreads();
        if (ki + 1 < nk) {
            int kt = (ki + 1) << 6;
            unsigned stoff = (unsigned)(((ki + 1) & 1) * 128 * SROW * 2);
#pragma unroll
            for (int i = 0; i < 4; i++) {
                int row = ldrow + i * 32;
                cp_async16(sA_u + stoff + (unsigned)((row * SROW + ldseg) * 2),
                           A + (size_t)(bm + row) * K + kt + ldseg);
                cp_async16(sB_u + stoff + (unsigned)((row * SROW + ldseg) * 2),
                           Bw + (size_t)(bn + row) * ldb + kt + ldseg);
            }
            asm volatile("cp.async.commit_group;");
        }
        unsigned cA_u = sA_u + (unsigned)((ki & 1) * 128 * SROW * 2);
        unsigned cB_u = sB_u + (unsigned)((ki & 1) * 128 * SROW * 2);
#pragma unroll
        for (int ks = 0; ks < 4; ks++) {
            int k0 = ks * 16;
            unsigned a[2][4], bf[8][2];
#pragma unroll
            for (int mi = 0; mi < 2; mi++) {
                unsigned addr = cA_u + (unsigned)(((wm + mi * 16) * SROW + k0) * 2) + laneA;
                LDSM4(a[mi][0], a[mi][1], a[mi][2], a[mi][3], addr);
            }
#pragma unroll
            for (int nj = 0; nj < 4; nj++) {
                unsigned addr = cB_u + (unsigned)(((wn + nj * 16) * SROW + k0) * 2) + laneB;
                LDSM4(bf[2 * nj][0], bf[2 * nj][1], bf[2 * nj + 1][0], bf[2 * nj + 1][1], addr);
            }
#pragma unroll
            for (int mi = 0; mi < 2; mi++)
#pragma unroll
                for (int ni = 0; ni < 8; ni++)
                    hmma(acc[mi][ni], a[mi][0], a[mi][1], a[mi][2], a[mi][3],
                         bf[ni][0], bf[ni][1]);
        }
        __syncthreads();
    }

#pragma unroll
    for (int mi = 0; mi < 2; mi++)
#pragma unroll
        for (int ni = 0; ni < 8; ni++)
#pragma unroll
            for (int h = 0; h < 2; h++) {
                int m = bm + wm + mi * 16 + r + h * 8;
                int n = bn + wn + ni * 8 + c;
                float v0 = acc[mi][ni][h * 2], v1 = acc[mi][ni][h * 2 + 1];
                if (mode == 0) {
                    *(__half2*)&reinterpret_cast<__half*>(Cout)[(size_t)m * N + n] =
                        __floats2half2_rn(v0, v1);
                } else if (mode == 1) {
                    *(float2*)&reinterpret_cast<float*>(Cout)[(size_t)m * N + n] =
                        make_float2(v0 + bias[n], v1 + bias[n + 1]);
                } else {
                    int b = m & 31, u = m >> 5;
                    *(float2*)&reinterpret_cast<float*>(Cout)
                        [(size_t)b * Un * Vn + (size_t)u * Vn + n] =
                        make_float2(v0 + bias[n], v1 + bias[n + 1]);
                }
            }
}

// ---------------- persistent-kernel helpers ----------------
__device__ __forceinline__ void stage_x(__half* sX, const __half* __restrict__ src,
                                        int stride, int tid)
{
#pragma unroll
    for (int it = 0; it < 8; it++) {
        int i = tid + it * 256;
        int sr = i >> 6;
        int j = i & 63;
        int cc = j >> 4, sg = (j & 15) * 8;
        *(uint4*)(sX + cc * 4352 + sr * 136 + sg) =
            *(const uint4*)(src + (size_t)sr * stride + cc * 128 + sg);
    }
}

__device__ __forceinline__ void mma_slab(const __half* sW, const __half* sX,
                                         float acc[4][4], int warp, int lane)
{
    int m = lane >> 2, kq = (lane & 3) * 2;
#pragma unroll
    for (int cc = 0; cc < 4; cc++) {
        const __half* wc = sW + cc * 6528;
        const __half* xc = sX + cc * 4352;
#pragma unroll
        for (int ks = 0; ks < 8; ks++) {
            int k0 = ks * 16;
            unsigned a0 = *(unsigned*)(wc + (warp * 16 + m) * 136 + k0 + kq);
            unsigned a1 = *(unsigned*)(wc + (warp * 16 + m + 8) * 136 + k0 + kq);
            unsigned a2 = *(unsigned*)(wc + (warp * 16 + m) * 136 + k0 + kq + 8);
            unsigned a3 = *(unsigned*)(wc + (warp * 16 + m + 8) * 136 + k0 + kq + 8);
#pragma unroll
            for (int nt = 0; nt < 4; nt++) {
                unsigned b0 = *(unsigned*)(xc + (nt * 8 + m) * 136 + k0 + kq);
                unsigned b1 = *(unsigned*)(xc + (nt * 8 + m) * 136 + k0 + kq + 8);
                hmma(acc[nt], a0, a1, a2, a3, b0, b1);
            }
        }
    }
}

// ---------------- persistent decode loop ----------------
__global__ __launch_bounds__(256, 1) void decode_persistent(
    const int* __restrict__ lens,
    const float* __restrict__ b_hh0, const float* __restrict__ b_ih1,
    const float* __restrict__ b_hh1)
{
    extern __shared__ __align__(16) char dynsm[];
    __half* sW = (__half*)dynsm;
    __half* sX = (__half*)(dynsm + SMEM_W_BYTES);
    char* scr = dynsm + SMEM_W_BYTES + SMEM_X_BYTES;

    int bid = blockIdx.x, tid = threadIdx.x;
    int warp = tid >> 5, lane = tid & 31;

    {
        const __half* Wsrc; int ld, coff, triplet, base;
        if (bid < 32)      { Wsrc = g_Wih0_h; ld = HEn; coff = Hn; triplet = 1; base = bid * 16; }
        else if (bid < 64) { Wsrc = g_Wih1_h; ld = Hn;  coff = 0;  triplet = 1; base = (bid - 32) * 16; }
        else if (bid < 96) { Wsrc = g_Whh0_h; ld = Hn;  coff = 0;  triplet = 0; base = (bid - 64) * 48; }
        else               { Wsrc = g_Whh1_h; ld = Hn;  coff = 0;  triplet = 0; base = (bid - 96) * 48; }
#pragma unroll
        for (int cc = 0; cc < 4; cc++) {
            for (int i = tid; i < 768; i += 256) {
                int sr = i >> 4, sg = (i & 15) * 8;
                int grow = triplet ? ((sr >> 4) * 512 + base + (sr & 15)) : (base + sr);
                *(uint4*)(sW + cc * 6528 + sr * 136 + sg) =
                    *(const uint4*)(Wsrc + (size_t)grow * ld + coff + cc * 128 + sg);
            }
        }
        __syncthreads();
    }

    int mylen = (bid < 64) ? lens[bid >> 1] : 0;

    for (int u = 0; u < Un; u++) {
        const float*  h0old  = g_h0buf + (u & 1) * BH;
        float*        h0new  = g_h0buf + ((u + 1) & 1) * BH;
        const float*  h1old  = g_h1buf + (u & 1) * BH;
        float*        h1new  = g_h1buf + ((u + 1) & 1) * BH;
        const __half* h0oldh = g_h0h + (u & 1) * BH;
        __half*       h0newh = g_h0h + ((u + 1) & 1) * BH;
        const __half* h1oldh = g_h1h + (u & 1) * BH;
        __half*       h1newh = g_h1h + ((u + 1) & 1) * BH;
        __half*       acts_u = g_acts + (size_t)u * Bn * HEn;

        if (bid < 64) {
            wait1(&g_cnt_g1, 32u * u);
            int b = bid >> 1;
            int eoff = (bid & 1) * 256;
            float* qs = (float*)scr;
            float* p  = qs + 512;
            float* red = p + 512;
            const float* q = (u == 0) ? (g_embQ + b * Hn) : (h1old + b * Hn);
            for (int i = tid; i < Hn; i += 256) qs[i] = q[i];
            __syncthreads();

            float sc0, sc1;
            {
                const uint4* r0 = (const uint4*)(g_encproj_h + ((size_t)b * Tn + tid) * Hn);
                const uint4* r1 = (const uint4*)(g_encproj_h + ((size_t)b * Tn + tid + 256) * Hn);
                float a00 = 0.f, a01 = 0.f, a10 = 0.f, a11 = 0.f;
#pragma unroll 4
                for (int i = 0; i < Hn / 8; i++) {
                    uint4 v0 = r0[i], v1 = r1[i];
                    const __half2* h0p = (const __half2*)&v0;
                    const __half2* h1p = (const __half2*)&v1;
                    const float* qq = qs + i * 8;
                    float2 f;
                    f = __half22float2(h0p[0]); a00 += f.x * qq[0] + f.y * qq[1];
                    f = __half22float2(h0p[1]); a01 += f.x * qq[2] + f.y * qq[3];
                    f = __half22float2(h0p[2]); a00 += f.x * qq[4] + f.y * qq[5];
                    f = __half22float2(h0p[3]); a01 += f.x * qq[6] + f.y * qq[7];
                    f = __half22float2(h1p[0]); a10 += f.x * qq[0] + f.y * qq[1];
                    f = __half22float2(h1p[1]); a11 += f.x * qq[2] + f.y * qq[3];
                    f = __half22float2(h1p[2]); a10 += f.x * qq[4] + f.y * qq[5];
                    f = __half22float2(h1p[3]); a11 += f.x * qq[6] + f.y * qq[7];
                }
                sc0 = (tid < mylen) ? (a00 + a01) : -INFINITY;
                sc1 = (tid + 256 < mylen) ? (a10 + a11) : -INFINITY;
            }
            float wm_ = fmaxf(sc0, sc1);
#pragma unroll
            for (int off = 16; off > 0; off >>= 1)
                wm_ = fmaxf(wm_, __shfl_xor_sync(0xFFFFFFFFu, wm_, off));
            if (lane == 0) red[warp] = wm_;
            __syncthreads();
            float mx = fmaxf(fmaxf(fmaxf(red[0], red[1]), fmaxf(red[2], red[3])),
                             fmaxf(fmaxf(red[4], red[5]), fmaxf(red[6], red[7])));
            float e0 = expf(sc0 - mx), e1 = expf(sc1 - mx);
            p[tid] = e0; p[tid + 256] = e1;
            float ws = e0 + e1;
#pragma unroll
            for (int off = 16; off > 0; off >>= 1)
                ws += __shfl_xor_sync(0xFFFFFFFFu, ws, off);
            if (lane == 0) red[warp] = ws;
            __syncthreads();
            float inv = 1.0f / (red[0] + red[1] + red[2] + red[3]
                              + red[4] + red[5] + red[6] + red[7]);

            int slot = tid & 31, tg = tid >> 5;
            const __half* encb = g_enc_h + (size_t)b * Tn * En + eoff + slot * 8;
            float cx[8];
#pragma unroll
            for (int j = 0; j < 8; j++) cx[j] = 0.0f;
#pragma unroll 4
            for (int it = 0; it < 64; it++) {
                int t = it * 8 + tg;
                uint4 v = *(const uint4*)(encb + (size_t)t * En);
                const __half2* hp = (const __half2*)&v;
                float w = p[t];
                float2 f;
                f = __half22float2(hp[0]); cx[0] += w * f.x; cx[1] += w * f.y;
                f = __half22float2(hp[1]); cx[2] += w * f.x; cx[3] += w * f.y;
                f = __half22float2(hp[2]); cx[4] += w * f.x; cx[5] += w * f.y;
                f = __half22float2(hp[3]); cx[6] += w * f.x; cx[7] += w * f.y;
            }
            float* part = (float*)sX;
            *(float4*)(part + tid * 8)     = make_float4(cx[0], cx[1], cx[2], cx[3]);
            *(float4*)(part + tid * 8 + 4) = make_float4(cx[4], cx[5], cx[6], cx[7]);
            __syncthreads();
            {
                int sl = tid >> 3, j = tid & 7;
                float s = 0.f;
#pragma unroll
                for (int t2 = 0; t2 < 8; t2++) s += part[((t2 << 5) + sl) * 8 + j];
                acts_u[(size_t)b * HEn + Hn + eoff + tid] = __float2half(s * inv);
            }
            signal(&g_cnt_attn);
        } else if (bid < 96) {
            wait1(&g_cnt_g0, 32u * u);
            stage_x(sX, h0oldh, Hn, tid);
            __syncthreads();
            float acc[4][4];
#pragma unroll
            for (int nt = 0; nt < 4; nt++)
#pragma unroll
                for (int q = 0; q < 4; q++) acc[nt][q] = 0.0f;
            if (warp < 3) {
                mma_slab(sW, sX, acc, warp, lane);
                int m = lane >> 2, nq = (lane & 3) * 2;
                int r0 = (bid - 64) * 48 + warp * 16 + m;
#pragma unroll
                for (int nt = 0; nt < 4; nt++) {
                    int n = nt * 8 + nq;
                    g_gh0[(size_t)n * G3H + r0]           = acc[nt][0];
                    g_gh0[(size_t)(n + 1) * G3H + r0]     = acc[nt][1];
                    g_gh0[(size_t)n * G3H + r0 + 8]       = acc[nt][2];
                    g_gh0[(size_t)(n + 1) * G3H + r0 + 8] = acc[nt][3];
                }
            }
            signal(&g_cnt_gh0);
        } else {
            wait1(&g_cnt_g1, 32u * u);
            stage_x(sX, h1oldh, Hn, tid);
            __syncthreads();
            float acc[4][4];
#pragma unroll
            for (int nt = 0; nt < 4; nt++)
#pragma unroll
                for (int q = 0; q < 4; q++) acc[nt][q] = 0.0f;
            if (warp < 3) {
                mma_slab(sW, sX, acc, warp, lane);
                int m = lane >> 2, nq = (lane & 3) * 2;
                int r0 = (bid - 96) * 48 + warp * 16 + m;
#pragma unroll
                for (int nt = 0; nt < 4; nt++) {
                    int n = nt * 8 + nq;
                    g_gh1[(size_t)n * G3H + r0]           = acc[nt][0];
                    g_gh1[(size_t)(n + 1) * G3H + r0]     = acc[nt][1];
                    g_gh1[(size_t)n * G3H + r0 + 8]       = acc[nt][2];
                    g_gh1[(size_t)(n + 1) * G3H + r0 + 8] = acc[nt][3];
                }
            }
            signal(&g_cnt_gh1);
        }

        if (bid < 32) {
            wait2(&g_cnt_attn, 64u * (u + 1), &g_cnt_gh0, 32u * (u + 1));
            int ibase = bid * 16;
            stage_x(sX, acts_u + Hn, HEn, tid);
            __syncthreads();
            float acc[4][4];
#pragma unroll
            for (int nt = 0; nt < 4; nt++)
#pragma unroll
                for (int q = 0; q < 4; q++) acc[nt][q] = 0.0f;
            float* gout = (float*)scr;
            if (warp < 3) {
                mma_slab(sW, sX, acc, warp, lane);
                int m = lane >> 2, nq = (lane & 3) * 2;
#pragma unroll
                for (int nt = 0; nt < 4; nt++) {
                    int n = nt * 8 + nq;
                    gout[warp * 528 + m * 33 + n]           = acc[nt][0];
                    gout[warp * 528 + m * 33 + n + 1]       = acc[nt][1];
                    gout[warp * 528 + (m + 8) * 33 + n]     = acc[nt][2];
                    gout[warp * 528 + (m + 8) * 33 + n + 1] = acc[nt][3];
                }
            }
            __syncthreads();
            const float* pre = g_gi0pre + (size_t)u * Bn * G3H;
#pragma unroll
            for (int it = 0; it < 2; it++) {
                int idx = tid + it * 256;
                int il = idx & 15, b = idx >> 4;
                int i = ibase + il;
                const float* pb = pre + (size_t)b * G3H;
                float gir = pb[i]        + gout[il * 33 + b];
                float giz = pb[512 + i]  + gout[528 + il * 33 + b];
                float gin = pb[1024 + i] + gout[1056 + il * 33 + b];
                const float* gb = g_gh0 + (size_t)b * G3H;
                float r = sigmoidf_(gir + gb[i] + b_hh0[i]);
                float z = sigmoidf_(giz + gb[512 + i] + b_hh0[512 + i]);
                float n = tanhf(gin + r * (gb[1024 + i] + b_hh0[1024 + i]));
                float hv = (1.0f - z) * n + z * h0old[b * Hn + i];
                h0new[b * Hn + i] = hv;
                h0newh[b * Hn + i] = __float2half(hv);
            }
            signal(&g_cnt_g0);
        }

        if (bid >= 32 && bid < 64) {
            wait2(&g_cnt_g0, 32u * (u + 1), &g_cnt_gh1, 32u * (u + 1));
            int ibase = (bid - 32) * 16;
            stage_x(sX, h0newh, Hn, tid);
            __syncthreads();
            float acc[4][4];
#pragma unroll
            for (int nt = 0; nt < 4; nt++)
#pragma unroll
                for (int q = 0; q < 4; q++) acc[nt][q] = 0.0f;
            float* gout = (float*)scr;
            if (warp < 3) {
                mma_slab(sW, sX, acc, warp, lane);
                int m = lane >> 2, nq = (lane & 3) * 2;
#pragma unroll
                for (int nt = 0; nt < 4; nt++) {
                    int n = nt * 8 + nq;
                    gout[warp * 528 + m * 33 + n]           = acc[nt][0];
                    gout[warp * 528 + m * 33 + n + 1]       = acc[nt][1];
                    gout[warp * 528 + (m + 8) * 33 + n]     = acc[nt][2];
                    gout[warp * 528 + (m + 8) * 33 + n + 1] = acc[nt][3];
                }
            }
            __syncthreads();
#pragma unroll
            for (int it = 0; it < 2; it++) {
                int idx = tid + it * 256;
                int il = idx & 15, b = idx >> 4;
                int i = ibase + il;
                float gir = b_ih1[i]        + gout[il * 33 + b];
                float giz = b_ih1[512 + i]  + gout[528 + il * 33 + b];
                float gin = b_ih1[1024 + i] + gout[1056 + il * 33 + b];
                const float* gb = g_gh1 + (size_t)b * G3H;
                float r = sigmoidf_(gir + gb[i] + b_hh1[i]);
                float z = sigmoidf_(giz + gb[512 + i] + b_hh1[512 + i]);
                float n = tanhf(gin + r * (gb[1024 + i] + b_hh1[1024 + i]));
                float hv = (1.0f - z) * n + z * h1old[b * Hn + i];
                h1new[b * Hn + i] = hv;
                __half hh = __float2half(hv);
                h1newh[b * Hn + i] = hh;
                acts_u[(size_t)b * HEn + i] = hh;
            }
            signal(&g_cnt_g1);
        }
    }
}

// ---------------- launch ----------------
extern "C" void kernel_launch(void* const* d_in, const int* in_sizes, int n_in,
                              void* d_out, int out_size)
{
    const float* encoder_out = (const float*)d_in[0];
    const int*   lens        = (const int*)d_in[1];
    const int*   din         = (const int*)d_in[2];
    const float* emb_table   = (const float*)d_in[3];
    const float* W_attn      = (const float*)d_in[4];
    const float* W_ih0       = (const float*)d_in[5];
    const float* W_hh0       = (const float*)d_in[6];
    const float* b_ih0       = (const float*)d_in[7];
    const float* b_hh0       = (const float*)d_in[8];
    const float* W_ih1       = (const float*)d_in[9];
    const float* W_hh1       = (const float*)d_in[10];
    const float* b_ih1       = (const float*)d_in[11];
    const float* b_hh1       = (const float*)d_in[12];
    const float* W_out       = (const float*)d_in[13];
    const float* b_out       = (const float*)d_in[14];
    float* out = (float*)d_out;

    __half *enc_h, *encproj_h, *Wattn_h, *Wih0_h, *embH, *acts, *Wout_h;
    float *gi0pre;
    cudaGetSymbolAddress((void**)&enc_h, g_enc_h);
    cudaGetSymbolAddress((void**)&encproj_h, g_encproj_h);
    cudaGetSymbolAddress((void**)&Wattn_h, g_Wattn_h);
    cudaGetSymbolAddress((void**)&Wih0_h, g_Wih0_h);
    cudaGetSymbolAddress((void**)&embH, g_embH);
    cudaGetSymbolAddress((void**)&acts, g_acts);
    cudaGetSymbolAddress((void**)&Wout_h, g_Wout_h);
    cudaGetSymbolAddress((void**)&gi0pre, g_gi0pre);

    static int smem_set = 0;
    if (!smem_set) {
        cudaFuncSetAttribute(decode_persistent,
                             cudaFuncAttributeMaxDynamicSharedMemorySize, SMEM_TOTAL_B);
        cudaFuncSetAttribute(gemm_h16,
                             cudaFuncAttributeMaxDynamicSharedMemorySize, GEMM_SMEM_B);
        smem_set = 1;
    }

    // launch 1: everything before the GEMMs in one kernel
    mega_prologue<<<(N4_TOTAL + 255) / 256, 256>>>(
        encoder_out, W_attn, W_ih0, W_ih1, W_hh0, W_hh1, W_out, din, emb_table);
    // launch 2: enc_proj
    gemm_h16<<<dim3(Hn / 128, (Bn * Tn) / 128), 256, GEMM_SMEM_B>>>(
        enc_h, Wattn_h, En, nullptr, encproj_h, Bn * Tn, Hn, En, 0, 0);
    // launch 3: gi0pre
    gemm_h16<<<dim3(G3H / 128, (Un * Bn) / 128), 256, GEMM_SMEM_B>>>(
        embH, Wih0_h, HEn, b_ih0, gi0pre, Un * Bn, G3H, Hn, 1, 0);
    // launch 4: decode (profiled slot)
    decode_persistent<<<NB, 256, SMEM_TOTAL_B>>>(lens, b_hh0, b_ih1, b_hh1);
    // launch 5: logits
    gemm_h16<<<dim3((Un * Bn) / 128, Vn / 128), 256, GEMM_SMEM_B>>>(
        acts, Wout_h, HEn, b_out, out, Un * Bn, Vn, HEn, 2, 1);
}

// round 12
// speedup vs baseline: 1.0825x; 1.0825x over previous
#include <cuda_runtime.h>
#include <cuda_fp16.h>
#include <math.h>
#include <stdint.h>

#define Bn 32
#define Tn 512
#define Un 64
#define Vn 32000
#define Hn 512
#define En 512
#define HEn 1024
#define G3H 1536
#define NB 128
#define BH (Bn * Hn)

#define SMEM_W_BYTES   52224
#define SMEM_X_BYTES   34816
#define SMEM_SCR_BYTES 16384
#define SMEM_TOTAL_B   (SMEM_W_BYTES + SMEM_X_BYTES + SMEM_SCR_BYTES)

#define GEMM_SMEM_B    73728

// ---------------- scratch (device globals) ----------------
__device__ __half g_enc_h[(size_t)Bn * Tn * En];
__device__ __half g_encproj_h[(size_t)Bn * Tn * Hn];
__device__ __half g_Wattn_h[Hn * En];
__device__ __half g_Wih0_h[G3H * HEn];
__device__ __half g_Wih1_h[G3H * Hn];
__device__ __half g_Whh0_h[G3H * Hn];
__device__ __half g_Whh1_h[G3H * Hn];
__device__ __half g_Wout_h[(size_t)Vn * HEn];
__device__ float  g_embQ[(size_t)Un * Bn * Hn];
__device__ __half g_embH[(size_t)Un * Bn * Hn];
__device__ float  g_gi0pre[(size_t)Un * Bn * G3H];
__device__ __half g_acts[(size_t)Un * Bn * HEn];
__device__ float  g_h0buf[2 * BH], g_h1buf[2 * BH];
__device__ __half g_h0h[2 * BH], g_h1h[2 * BH];
__device__ float  g_gh0[Bn * G3H], g_gh1[Bn * G3H];
__device__ __align__(128) unsigned g_cnt_attn;
__device__ __align__(128) unsigned g_cnt_gh0;
__device__ __align__(128) unsigned g_cnt_gh1;
__device__ __align__(128) unsigned g_cnt_g0;
__device__ __align__(128) unsigned g_cnt_g1;

__device__ __forceinline__ float sigmoidf_(float x) { return 1.0f / (1.0f + expf(-x)); }

__device__ __forceinline__ void hmma(float* c, unsigned a0, unsigned a1, unsigned a2,
                                     unsigned a3, unsigned b0, unsigned b1) {
    asm volatile(
        "mma.sync.aligned.m16n8k16.row.col.f32.f16.f16.f32 "
        "{%0,%1,%2,%3},{%4,%5,%6,%7},{%8,%9},{%0,%1,%2,%3};"
        : "+f"(c[0]), "+f"(c[1]), "+f"(c[2]), "+f"(c[3])
        : "r"(a0), "r"(a1), "r"(a2), "r"(a3), "r"(b0), "r"(b1));
}

__device__ __forceinline__ void cp_async16(unsigned saddr, const void* gptr) {
    asm volatile("cp.async.cg.shared.global [%0], [%1], 16;" :: "r"(saddr), "l"(gptr));
}

#define LDSM4(d0, d1, d2, d3, addr) \
    asm volatile("ldmatrix.sync.aligned.m8n8.x4.shared.b16 {%0,%1,%2,%3}, [%4];" \
        : "=r"(d0), "=r"(d1), "=r"(d2), "=r"(d3) : "r"(addr))

// ---------------- point-to-point sync (pure spin, padded counters) ----------------
__device__ __forceinline__ void wait1(unsigned* p, unsigned tgt) {
    if (threadIdx.x == 0) {
        while (*(volatile unsigned*)p < tgt) { }
        __threadfence();
    }
    __syncthreads();
}
__device__ __forceinline__ void wait2(unsigned* pa, unsigned ta, unsigned* pb, unsigned tb) {
    if (threadIdx.x == 0) {
        while (*(volatile unsigned*)pa < ta) { }
        while (*(volatile unsigned*)pb < tb) { }
        __threadfence();
    }
    __syncthreads();
}
__device__ __forceinline__ void signal(unsigned* cnt) {
    __syncthreads();
    if (threadIdx.x == 0) { __threadfence(); atomicAdd(cnt, 1u); }
}

// ---------------- mega prologue ----------------
#define N4_ENC   2097152
#define N4_WATTN 65536
#define N4_WIH0  393216
#define N4_WIH1  196608
#define N4_WHH0  196608
#define N4_WHH1  196608
#define N4_WOUT  8192000
#define N4_TOTAL (N4_ENC + N4_WATTN + N4_WIH0 + N4_WIH1 + N4_WHH0 + N4_WHH1 + N4_WOUT)

__global__ void mega_prologue(const float* __restrict__ enc, const float* __restrict__ wat,
                              const float* __restrict__ wi0, const float* __restrict__ wi1,
                              const float* __restrict__ wh0, const float* __restrict__ wh1,
                              const float* __restrict__ wo,
                              const int* __restrict__ din, const float* __restrict__ table)
{
    long long i = (long long)blockIdx.x * 256 + threadIdx.x;

    if (i < BH) {
        g_h0buf[i] = 0.0f; g_h1buf[i] = 0.0f;
        g_h0h[i] = __float2half(0.0f); g_h1h[i] = __float2half(0.0f);
    }
    if (i == 0) {
        g_cnt_attn = 0; g_cnt_gh0 = 0; g_cnt_gh1 = 0; g_cnt_g0 = 0; g_cnt_g1 = 0;
    }

    if (i < Un * Bn * Hn) {
        int h = (int)i & (Hn - 1);
        int m = (int)(i >> 9);
        int u = m >> 5, b = m & 31;
        float v = table[(size_t)din[b * Un + u] * Hn + h];
        g_embQ[i] = v;
        g_embH[i] = __float2half(v);
    }

    if (i < N4_TOTAL) {
        const float* src; __half* dst; long long off = i;
        if (off < N4_ENC)                 { src = enc; dst = g_enc_h; }
        else if ((off -= N4_ENC)   < N4_WATTN) { src = wat; dst = g_Wattn_h; }
        else if ((off -= N4_WATTN) < N4_WIH0)  { src = wi0; dst = g_Wih0_h; }
        else if ((off -= N4_WIH0)  < N4_WIH1)  { src = wi1; dst = g_Wih1_h; }
        else if ((off -= N4_WIH1)  < N4_WHH0)  { src = wh0; dst = g_Whh0_h; }
        else if ((off -= N4_WHH0)  < N4_WHH1)  { src = wh1; dst = g_Whh1_h; }
        else { off -= N4_WHH1; src = wo; dst = g_Wout_h; }
        float4 v = reinterpret_cast<const float4*>(src)[off];
        reinterpret_cast<__half2*>(dst)[2 * off]     = __floats2half2_rn(v.x, v.y);
        reinterpret_cast<__half2*>(dst)[2 * off + 1] = __floats2half2_rn(v.z, v.w);
    }
}

// ---------------- pipelined fp16 GEMM with ldmatrix ----------------
#define SROW 72
__global__ __launch_bounds__(256) void gemm_h16(
    const __half* __restrict__ A, const __half* __restrict__ Bw, int ldb,
    const float* __restrict__ bias, void* __restrict__ Cout,
    int M, int N, int K, int mode, int swap)
{
    extern __shared__ __align__(16) __half gsm[];
    __half* sA = gsm;
    __half* sB = gsm + 2 * 128 * SROW;

    int tid = threadIdx.x, lane = tid & 31, warp = tid >> 5;
    int wm = (warp >> 1) * 32;
    int wn = (warp & 1) * 64;
    int bm = (swap ? blockIdx.x : blockIdx.y) * 128;
    int bn = (swap ? blockIdx.y : blockIdx.x) * 128;
    int r = lane >> 2, c = (lane & 3) * 2;

    unsigned sA_u = (unsigned)__cvta_generic_to_shared(sA);
    unsigned sB_u = (unsigned)__cvta_generic_to_shared(sB);

    int ri = lane & 7, g = lane >> 3;
    unsigned laneA = (unsigned)(((ri + (g & 1) * 8) * SROW + (g >> 1) * 8) * 2);
    unsigned laneB = (unsigned)(((ri + (g >> 1) * 8) * SROW + (g & 1) * 8) * 2);

    int ldrow = tid >> 3, ldseg = (tid & 7) * 8;

    float acc[2][8][4];
#pragma unroll
    for (int mi = 0; mi < 2; mi++)
#pragma unroll
        for (int ni = 0; ni < 8; ni++)
#pragma unroll
            for (int q = 0; q < 4; q++) acc[mi][ni][q] = 0.0f;

    int nk = K >> 6;

#pragma unroll
    for (int i = 0; i < 4; i++) {
        int row = ldrow + i * 32;
        cp_async16(sA_u + (unsigned)((row * SROW + ldseg) * 2),
                   A + (size_t)(bm + row) * K + ldseg);
        cp_async16(sB_u + (unsigned)((row * SROW + ldseg) * 2),
                   Bw + (size_t)(bn + row) * ldb + ldseg);
    }
    asm volatile("cp.async.commit_group;");

    for (int ki = 0; ki < nk; ki++) {
        asm volatile("cp.async.wait_group 0;");
        __syncthreads();
        if (ki + 1 < nk) {
            int kt = (ki + 1) << 6;
            unsigned stoff = (unsigned)(((ki + 1) & 1) * 128 * SROW * 2);
#pragma unroll
            for (int i = 0; i < 4; i++) {
                int row = ldrow + i * 32;
                cp_async16(sA_u + stoff + (unsigned)((row * SROW + ldseg) * 2),
                           A + (size_t)(bm + row) * K + kt + ldseg);
                cp_async16(sB_u + stoff + (unsigned)((row * SROW + ldseg) * 2),
                           Bw + (size_t)(bn + row) * ldb + kt + ldseg);
            }
            asm volatile("cp.async.commit_group;");
        }
        unsigned cA_u = sA_u + (unsigned)((ki & 1) * 128 * SROW * 2);
        unsigned cB_u = sB_u + (unsigned)((ki & 1) * 128 * SROW * 2);
#pragma unroll
        for (int ks = 0; ks < 4; ks++) {
            int k0 = ks * 16;
            unsigned a[2][4], bf[8][2];
#pragma unroll
            for (int mi = 0; mi < 2; mi++) {
                unsigned addr = cA_u + (unsigned)(((wm + mi * 16) * SROW + k0) * 2) + laneA;
                LDSM4(a[mi][0], a[mi][1], a[mi][2], a[mi][3], addr);
            }
#pragma unroll
            for (int nj = 0; nj < 4; nj++) {
                unsigned addr = cB_u + (unsigned)(((wn + nj * 16) * SROW + k0) * 2) + laneB;
                LDSM4(bf[2 * nj][0], bf[2 * nj][1], bf[2 * nj + 1][0], bf[2 * nj + 1][1], addr);
            }
#pragma unroll
            for (int mi = 0; mi < 2; mi++)
#pragma unroll
                for (int ni = 0; ni < 8; ni++)
                    hmma(acc[mi][ni], a[mi][0], a[mi][1], a[mi][2], a[mi][3],
                         bf[ni][0], bf[ni][1]);
        }
        __syncthreads();
    }

#pragma unroll
    for (int mi = 0; mi < 2; mi++)
#pragma unroll
        for (int ni = 0; ni < 8; ni++)
#pragma unroll
            for (int h = 0; h < 2; h++) {
                int m = bm + wm + mi * 16 + r + h * 8;
                int n = bn + wn + ni * 8 + c;
                float v0 = acc[mi][ni][h * 2], v1 = acc[mi][ni][h * 2 + 1];
                if (mode == 0) {
                    *(__half2*)&reinterpret_cast<__half*>(Cout)[(size_t)m * N + n] =
                        __floats2half2_rn(v0, v1);
                } else if (mode == 1) {
                    *(float2*)&reinterpret_cast<float*>(Cout)[(size_t)m * N + n] =
                        make_float2(v0 + bias[n], v1 + bias[n + 1]);
                } else {
                    int b = m & 31, u = m >> 5;
                    *(float2*)&reinterpret_cast<float*>(Cout)
                        [(size_t)b * Un * Vn + (size_t)u * Vn + n] =
                        make_float2(v0 + bias[n], v1 + bias[n + 1]);
                }
            }
}

// ---------------- persistent-kernel helpers ----------------
__device__ __forceinline__ void stage_x(__half* sX, const __half* __restrict__ src,
                                        int stride, int tid)
{
#pragma unroll
    for (int it = 0; it < 8; it++) {
        int i = tid + it * 256;
        int sr = i >> 6;
        int j = i & 63;
        int cc = j >> 4, sg = (j & 15) * 8;
        *(uint4*)(sX + cc * 4352 + sr * 136 + sg) =
            *(const uint4*)(src + (size_t)sr * stride + cc * 128 + sg);
    }
}

__device__ __forceinline__ void mma_slab(const __half* sW, const __half* sX,
                                         float acc[4][4], int warp, int lane)
{
    int m = lane >> 2, kq = (lane & 3) * 2;
#pragma unroll
    for (int cc = 0; cc < 4; cc++) {
        const __half* wc = sW + cc * 6528;
        const __half* xc = sX + cc * 4352;
#pragma unroll
        for (int ks = 0; ks < 8; ks++) {
            int k0 = ks * 16;
            unsigned a0 = *(unsigned*)(wc + (warp * 16 + m) * 136 + k0 + kq);
            unsigned a1 = *(unsigned*)(wc + (warp * 16 + m + 8) * 136 + k0 + kq);
            unsigned a2 = *(unsigned*)(wc + (warp * 16 + m) * 136 + k0 + kq + 8);
            unsigned a3 = *(unsigned*)(wc + (warp * 16 + m + 8) * 136 + k0 + kq + 8);
#pragma unroll
            for (int nt = 0; nt < 4; nt++) {
                unsigned b0 = *(unsigned*)(xc + (nt * 8 + m) * 136 + k0 + kq);
                unsigned b1 = *(unsigned*)(xc + (nt * 8 + m) * 136 + k0 + kq + 8);
                hmma(acc[nt], a0, a1, a2, a3, b0, b1);
            }
        }
    }
}

// ---------------- persistent decode loop ----------------
__global__ __launch_bounds__(256, 1) void decode_persistent(
    const int* __restrict__ lens,
    const float* __restrict__ b_hh0, const float* __restrict__ b_ih1,
    const float* __restrict__ b_hh1)
{
    extern __shared__ __align__(16) char dynsm[];
    __half* sW = (__half*)dynsm;
    __half* sX = (__half*)(dynsm + SMEM_W_BYTES);
    char* scr = dynsm + SMEM_W_BYTES + SMEM_X_BYTES;

    int bid = blockIdx.x, tid = threadIdx.x;
    int warp = tid >> 5, lane = tid & 31;

    {
        const __half* Wsrc; int ld, coff, triplet, base;
        if (bid < 32)      { Wsrc = g_Wih0_h; ld = HEn; coff = Hn; triplet = 1; base = bid * 16; }
        else if (bid < 64) { Wsrc = g_Wih1_h; ld = Hn;  coff = 0;  triplet = 1; base = (bid - 32) * 16; }
        else if (bid < 96) { Wsrc = g_Whh0_h; ld = Hn;  coff = 0;  triplet = 0; base = (bid - 64) * 48; }
        else               { Wsrc = g_Whh1_h; ld = Hn;  coff = 0;  triplet = 0; base = (bid - 96) * 48; }
#pragma unroll
        for (int cc = 0; cc < 4; cc++) {
            for (int i = tid; i < 768; i += 256) {
                int sr = i >> 4, sg = (i & 15) * 8;
                int grow = triplet ? ((sr >> 4) * 512 + base + (sr & 15)) : (base + sr);
                *(uint4*)(sW + cc * 6528 + sr * 136 + sg) =
                    *(const uint4*)(Wsrc + (size_t)grow * ld + coff + cc * 128 + sg);
            }
        }
        __syncthreads();
    }

    int mylen = (bid < 64) ? lens[bid >> 1] : 0;

    for (int u = 0; u < Un; u++) {
        const float*  h0old  = g_h0buf + (u & 1) * BH;
        float*        h0new  = g_h0buf + ((u + 1) & 1) * BH;
        const float*  h1old  = g_h1buf + (u & 1) * BH;
        float*        h1new  = g_h1buf + ((u + 1) & 1) * BH;
        const __half* h0oldh = g_h0h + (u & 1) * BH;
        __half*       h0newh = g_h0h + ((u + 1) & 1) * BH;
        const __half* h1oldh = g_h1h + (u & 1) * BH;
        __half*       h1newh = g_h1h + ((u + 1) & 1) * BH;
        __half*       acts_u = g_acts + (size_t)u * Bn * HEn;

        if (bid < 64) {
            // ===== fused attention (deep-MLP loads) =====
            wait1(&g_cnt_g1, 32u * u);
            int b = bid >> 1;
            int eoff = (bid & 1) * 256;
            float* qs = (float*)scr;
            float* p  = qs + 512;
            float* red = p + 512;
            const float* q = (u == 0) ? (g_embQ + b * Hn) : (h1old + b * Hn);
            for (int i = tid; i < Hn; i += 256) qs[i] = q[i];
            __syncthreads();

            float sc0, sc1;
            {
                const uint4* r0 = (const uint4*)(g_encproj_h + ((size_t)b * Tn + tid) * Hn);
                const uint4* r1 = (const uint4*)(g_encproj_h + ((size_t)b * Tn + tid + 256) * Hn);
                float a00 = 0.f, a01 = 0.f, a10 = 0.f, a11 = 0.f;
#pragma unroll
                for (int ib = 0; ib < 8; ib++) {          // FIXED: 8 batches x 8 uint4 = 64
                    uint4 v0[8], v1[8];
#pragma unroll
                    for (int j = 0; j < 8; j++) { v0[j] = r0[ib * 8 + j]; v1[j] = r1[ib * 8 + j]; }
#pragma unroll
                    for (int j = 0; j < 8; j++) {
                        int i = ib * 8 + j;
                        const __half2* h0p = (const __half2*)&v0[j];
                        const __half2* h1p = (const __half2*)&v1[j];
                        const float* qq = qs + i * 8;
                        float2 f;
                        f = __half22float2(h0p[0]); a00 += f.x * qq[0] + f.y * qq[1];
                        f = __half22float2(h0p[1]); a01 += f.x * qq[2] + f.y * qq[3];
                        f = __half22float2(h0p[2]); a00 += f.x * qq[4] + f.y * qq[5];
                        f = __half22float2(h0p[3]); a01 += f.x * qq[6] + f.y * qq[7];
                        f = __half22float2(h1p[0]); a10 += f.x * qq[0] + f.y * qq[1];
                        f = __half22float2(h1p[1]); a11 += f.x * qq[2] + f.y * qq[3];
                        f = __half22float2(h1p[2]); a10 += f.x * qq[4] + f.y * qq[5];
                        f = __half22float2(h1p[3]); a11 += f.x * qq[6] + f.y * qq[7];
                    }
                }
                sc0 = (tid < mylen) ? (a00 + a01) : -INFINITY;
                sc1 = (tid + 256 < mylen) ? (a10 + a11) : -INFINITY;
            }
            float wm_ = fmaxf(sc0, sc1);
#pragma unroll
            for (int off = 16; off > 0; off >>= 1)
                wm_ = fmaxf(wm_, __shfl_xor_sync(0xFFFFFFFFu, wm_, off));
            if (lane == 0) red[warp] = wm_;
            __syncthreads();
            float mx = fmaxf(fmaxf(fmaxf(red[0], red[1]), fmaxf(red[2], red[3])),
                             fmaxf(fmaxf(red[4], red[5]), fmaxf(red[6], red[7])));
            float e0 = expf(sc0 - mx), e1 = expf(sc1 - mx);
            p[tid] = e0; p[tid + 256] = e1;
            float ws = e0 + e1;
#pragma unroll
            for (int off = 16; off > 0; off >>= 1)
                ws += __shfl_xor_sync(0xFFFFFFFFu, ws, off);
            if (lane == 0) red[warp] = ws;
            __syncthreads();
            float inv = 1.0f / (red[0] + red[1] + red[2] + red[3]
                              + red[4] + red[5] + red[6] + red[7]);

            // context with batched loads (8 uint4 in flight)
            int slot = tid & 31, tg = tid >> 5;
            const __half* encb = g_enc_h + (size_t)b * Tn * En + eoff + slot * 8;
            float cx[8];
#pragma unroll
            for (int j = 0; j < 8; j++) cx[j] = 0.0f;
#pragma unroll
            for (int ob = 0; ob < 8; ob++) {
                uint4 v[8];
#pragma unroll
                for (int j = 0; j < 8; j++) {
                    int t = (ob * 8 + j) * 8 + tg;
                    v[j] = *(const uint4*)(encb + (size_t)t * En);
                }
#pragma unroll
                for (int j = 0; j < 8; j++) {
                    int t = (ob * 8 + j) * 8 + tg;
                    const __half2* hp = (const __half2*)&v[j];
                    float w = p[t];
                    float2 f;
                    f = __half22float2(hp[0]); cx[0] += w * f.x; cx[1] += w * f.y;
                    f = __half22float2(hp[1]); cx[2] += w * f.x; cx[3] += w * f.y;
                    f = __half22float2(hp[2]); cx[4] += w * f.x; cx[5] += w * f.y;
                    f = __half22float2(hp[3]); cx[6] += w * f.x; cx[7] += w * f.y;
                }
            }
            float* part = (float*)sX;
            *(float4*)(part + tid * 8)     = make_float4(cx[0], cx[1], cx[2], cx[3]);
            *(float4*)(part + tid * 8 + 4) = make_float4(cx[4], cx[5], cx[6], cx[7]);
            __syncthreads();
            {
                int sl = tid >> 3, j = tid & 7;
                float s = 0.f;
#pragma unroll
                for (int t2 = 0; t2 < 8; t2++) s += part[((t2 << 5) + sl) * 8 + j];
                acts_u[(size_t)b * HEn + Hn + eoff + tid] = __float2half(s * inv);
            }
            signal(&g_cnt_attn);
        } else if (bid < 96) {
            wait1(&g_cnt_g0, 32u * u);
            stage_x(sX, h0oldh, Hn, tid);
            __syncthreads();
            float acc[4][4];
#pragma unroll
            for (int nt = 0; nt < 4; nt++)
#pragma unroll
                for (int q = 0; q < 4; q++) acc[nt][q] = 0.0f;
            if (warp < 3) {
                mma_slab(sW, sX, acc, warp, lane);
                int m = lane >> 2, nq = (lane & 3) * 2;
                int r0 = (bid - 64) * 48 + warp * 16 + m;
#pragma unroll
                for (int nt = 0; nt < 4; nt++) {
                    int n = nt * 8 + nq;
                    g_gh0[(size_t)n * G3H + r0]           = acc[nt][0];
                    g_gh0[(size_t)(n + 1) * G3H + r0]     = acc[nt][1];
                    g_gh0[(size_t)n * G3H + r0 + 8]       = acc[nt][2];
                    g_gh0[(size_t)(n + 1) * G3H + r0 + 8] = acc[nt][3];
                }
            }
            signal(&g_cnt_gh0);
        } else {
            wait1(&g_cnt_g1, 32u * u);
            stage_x(sX, h1oldh, Hn, tid);
            __syncthreads();
            float acc[4][4];
#pragma unroll
            for (int nt = 0; nt < 4; nt++)
#pragma unroll
                for (int q = 0; q < 4; q++) acc[nt][q] = 0.0f;
            if (warp < 3) {
                mma_slab(sW, sX, acc, warp, lane);
                int m = lane >> 2, nq = (lane & 3) * 2;
                int r0 = (bid - 96) * 48 + warp * 16 + m;
#pragma unroll
                for (int nt = 0; nt < 4; nt++) {
                    int n = nt * 8 + nq;
                    g_gh1[(size_t)n * G3H + r0]           = acc[nt][0];
                    g_gh1[(size_t)(n + 1) * G3H + r0]     = acc[nt][1];
                    g_gh1[(size_t)n * G3H + r0 + 8]       = acc[nt][2];
                    g_gh1[(size_t)(n + 1) * G3H + r0 + 8] = acc[nt][3];
                }
            }
            signal(&g_cnt_gh1);
        }

        if (bid < 32) {
            wait2(&g_cnt_attn, 64u * (u + 1), &g_cnt_gh0, 32u * (u + 1));
            int ibase = bid * 16;
            stage_x(sX, acts_u + Hn, HEn, tid);
            __syncthreads();
            float acc[4][4];
#pragma unroll
            for (int nt = 0; nt < 4; nt++)
#pragma unroll
                for (int q = 0; q < 4; q++) acc[nt][q] = 0.0f;
            float* gout = (float*)scr;
            if (warp < 3) {
                mma_slab(sW, sX, acc, warp, lane);
                int m = lane >> 2, nq = (lane & 3) * 2;
#pragma unroll
                for (int nt = 0; nt < 4; nt++) {
                    int n = nt * 8 + nq;
                    gout[warp * 528 + m * 33 + n]           = acc[nt][0];
                    gout[warp * 528 + m * 33 + n + 1]       = acc[nt][1];
                    gout[warp * 528 + (m + 8) * 33 + n]     = acc[nt][2];
                    gout[warp * 528 + (m + 8) * 33 + n + 1] = acc[nt][3];
                }
            }
            __syncthreads();
            const float* pre = g_gi0pre + (size_t)u * Bn * G3H;
#pragma unroll
            for (int it = 0; it < 2; it++) {
                int idx = tid + it * 256;
                int il = idx & 15, b = idx >> 4;
                int i = ibase + il;
                const float* pb = pre + (size_t)b * G3H;
                float gir = pb[i]        + gout[il * 33 + b];
                float giz = pb[512 + i]  + gout[528 + il * 33 + b];
                float gin = pb[1024 + i] + gout[1056 + il * 33 + b];
                const float* gb = g_gh0 + (size_t)b * G3H;
                float r = sigmoidf_(gir + gb[i] + b_hh0[i]);
                float z = sigmoidf_(giz + gb[512 + i] + b_hh0[512 + i]);
                float n = tanhf(gin + r * (gb[1024 + i] + b_hh0[1024 + i]));
                float hv = (1.0f - z) * n + z * h0old[b * Hn + i];
                h0new[b * Hn + i] = hv;
                h0newh[b * Hn + i] = __float2half(hv);
            }
            signal(&g_cnt_g0);
        }

        if (bid >= 32 && bid < 64) {
            wait2(&g_cnt_g0, 32u * (u + 1), &g_cnt_gh1, 32u * (u + 1));
            int ibase = (bid - 32) * 16;
            stage_x(sX, h0newh, Hn, tid);
            __syncthreads();
            float acc[4][4];
#pragma unroll
            for (int nt = 0; nt < 4; nt++)
#pragma unroll
                for (int q = 0; q < 4; q++) acc[nt][q] = 0.0f;
            float* gout = (float*)scr;
            if (warp < 3) {
                mma_slab(sW, sX, acc, warp, lane);
                int m = lane >> 2, nq = (lane & 3) * 2;
#pragma unroll
                for (int nt = 0; nt < 4; nt++) {
                    int n = nt * 8 + nq;
                    gout[warp * 528 + m * 33 + n]           = acc[nt][0];
                    gout[warp * 528 + m * 33 + n + 1]       = acc[nt][1];
                    gout[warp * 528 + (m + 8) * 33 + n]     = acc[nt][2];
                    gout[warp * 528 + (m + 8) * 33 + n + 1] = acc[nt][3];
                }
            }
            __syncthreads();
#pragma unroll
            for (int it = 0; it < 2; it++) {
                int idx = tid + it * 256;
                int il = idx & 15, b = idx >> 4;
                int i = ibase + il;
                float gir = b_ih1[i]        + gout[il * 33 + b];
                float giz = b_ih1[512 + i]  + gout[528 + il * 33 + b];
                float gin = b_ih1[1024 + i] + gout[1056 + il * 33 + b];
                const float* gb = g_gh1 + (size_t)b * G3H;
                float r = sigmoidf_(gir + gb[i] + b_hh1[i]);
                float z = sigmoidf_(giz + gb[512 + i] + b_hh1[512 + i]);
                float n = tanhf(gin + r * (gb[1024 + i] + b_hh1[1024 + i]));
                float hv = (1.0f - z) * n + z * h1old[b * Hn + i];
                h1new[b * Hn + i] = hv;
                __half hh = __float2half(hv);
                h1newh[b * Hn + i] = hh;
                acts_u[(size_t)b * HEn + i] = hh;
            }
            signal(&g_cnt_g1);
        }
    }
}

// ---------------- launch ----------------
extern "C" void kernel_launch(void* const* d_in, const int* in_sizes, int n_in,
                              void* d_out, int out_size)
{
    const float* encoder_out = (const float*)d_in[0];
    const int*   lens        = (const int*)d_in[1];
    const int*   din         = (const int*)d_in[2];
    const float* emb_table   = (const float*)d_in[3];
    const float* W_attn      = (const float*)d_in[4];
    const float* W_ih0       = (const float*)d_in[5];
    const float* W_hh0       = (const float*)d_in[6];
    const float* b_ih0       = (const float*)d_in[7];
    const float* b_hh0       = (const float*)d_in[8];
    const float* W_ih1       = (const float*)d_in[9];
    const float* W_hh1       = (const float*)d_in[10];
    const float* b_ih1       = (const float*)d_in[11];
    const float* b_hh1       = (const float*)d_in[12];
    const float* W_out       = (const float*)d_in[13];
    const float* b_out       = (const float*)d_in[14];
    float* out = (float*)d_out;

    __half *enc_h, *encproj_h, *Wattn_h, *Wih0_h, *embH, *acts, *Wout_h;
    float *gi0pre;
    cudaGetSymbolAddress((void**)&enc_h, g_enc_h);
    cudaGetSymbolAddress((void**)&encproj_h, g_encproj_h);
    cudaGetSymbolAddress((void**)&Wattn_h, g_Wattn_h);
    cudaGetSymbolAddress((void**)&Wih0_h, g_Wih0_h);
    cudaGetSymbolAddress((void**)&embH, g_embH);
    cudaGetSymbolAddress((void**)&acts, g_acts);
    cudaGetSymbolAddress((void**)&Wout_h, g_Wout_h);
    cudaGetSymbolAddress((void**)&gi0pre, g_gi0pre);

    static int smem_set = 0;
    if (!smem_set) {
        cudaFuncSetAttribute(decode_persistent,
                             cudaFuncAttributeMaxDynamicSharedMemorySize, SMEM_TOTAL_B);
        cudaFuncSetAttribute(gemm_h16,
                             cudaFuncAttributeMaxDynamicSharedMemorySize, GEMM_SMEM_B);
        smem_set = 1;
    }

    mega_prologue<<<(N4_TOTAL + 255) / 256, 256>>>(
        encoder_out, W_attn, W_ih0, W_ih1, W_hh0, W_hh1, W_out, din, emb_table);
    gemm_h16<<<dim3(Hn / 128, (Bn * Tn) / 128), 256, GEMM_SMEM_B>>>(
        enc_h, Wattn_h, En, nullptr, encproj_h, Bn * Tn, Hn, En, 0, 0);
    gemm_h16<<<dim3(G3H / 128, (Un * Bn) / 128), 256, GEMM_SMEM_B>>>(
        embH, Wih0_h, HEn, b_ih0, gi0pre, Un * Bn, G3H, Hn, 1, 0);
    decode_persistent<<<NB, 256, SMEM_TOTAL_B>>>(lens, b_hh0, b_ih1, b_hh1);
    gemm_h16<<<dim3((Un * Bn) / 128, Vn / 128), 256, GEMM_SMEM_B>>>(
        acts, Wout_h, HEn, b_out, out, Un * Bn, Vn, HEn, 2, 1);
}

// round 13
// speedup vs baseline: 1.0909x; 1.0077x over previous
#include <cuda_runtime.h>
#include <cuda_fp16.h>
#include <math.h>
#include <stdint.h>

#define Bn 32
#define Tn 512
#define Un 64
#define Vn 32000
#define Hn 512
#define En 512
#define HEn 1024
#define G3H 1536
#define NB 128
#define BH (Bn * Hn)

#define SMEM_W_BYTES   52224
#define SMEM_X_BYTES   34816
#define SMEM_SCR_BYTES 16384
#define SMEM_TOTAL_B   (SMEM_W_BYTES + SMEM_X_BYTES + SMEM_SCR_BYTES)

#define GEMM_SMEM_B    73728

// ---------------- scratch (device globals) ----------------
__device__ __half g_enc_h[(size_t)Bn * Tn * En];
__device__ __half g_encproj_h[(size_t)Bn * Tn * Hn];
__device__ __half g_Wattn_h[Hn * En];
__device__ __half g_Wih0_h[G3H * HEn];
__device__ __half g_Wih1_h[G3H * Hn];
__device__ __half g_Whh0_h[G3H * Hn];
__device__ __half g_Whh1_h[G3H * Hn];
__device__ __half g_Wout_h[(size_t)Vn * HEn];
__device__ float  g_embQ[(size_t)Un * Bn * Hn];
__device__ __half g_embH[(size_t)Un * Bn * Hn];
__device__ float  g_gi0pre[(size_t)Un * Bn * G3H];
__device__ __half g_acts[(size_t)Un * Bn * HEn];
__device__ float  g_h0buf[2 * BH], g_h1buf[2 * BH];
__device__ __half g_h0h[2 * BH], g_h1h[2 * BH];
__device__ float  g_gh0[Bn * G3H], g_gh1[Bn * G3H];
// per-block progress flags (store-based; no atomics)
__device__ __align__(128) volatile unsigned g_fattn[64];
__device__ __align__(128) volatile unsigned g_fgh0[32];
__device__ __align__(128) volatile unsigned g_fgh1[32];
__device__ __align__(128) volatile unsigned g_fg0[32];
__device__ __align__(128) volatile unsigned g_fg1[32];

__device__ __forceinline__ float sigmoidf_(float x) { return 1.0f / (1.0f + expf(-x)); }

__device__ __forceinline__ void hmma(float* c, unsigned a0, unsigned a1, unsigned a2,
                                     unsigned a3, unsigned b0, unsigned b1) {
    asm volatile(
        "mma.sync.aligned.m16n8k16.row.col.f32.f16.f16.f32 "
        "{%0,%1,%2,%3},{%4,%5,%6,%7},{%8,%9},{%0,%1,%2,%3};"
        : "+f"(c[0]), "+f"(c[1]), "+f"(c[2]), "+f"(c[3])
        : "r"(a0), "r"(a1), "r"(a2), "r"(a3), "r"(b0), "r"(b1));
}

__device__ __forceinline__ void cp_async16(unsigned saddr, const void* gptr) {
    asm volatile("cp.async.cg.shared.global [%0], [%1], 16;" :: "r"(saddr), "l"(gptr));
}

#define LDSM4(d0, d1, d2, d3, addr) \
    asm volatile("ldmatrix.sync.aligned.m8n8.x4.shared.b16 {%0,%1,%2,%3}, [%4];" \
        : "=r"(d0), "=r"(d1), "=r"(d2), "=r"(d3) : "r"(addr))

// ---------------- store-flag sync primitives ----------------
// consumers: tid<n poll distinct slots in parallel; then one IVALL fence.
__device__ __forceinline__ void wait_flags(volatile unsigned* f, int n,
                                           unsigned tgt, int tid) {
    if (tid < n) { while (f[tid] < tgt) { } }
    __syncthreads();
    if (tid == 0) __threadfence();
    __syncthreads();
}
__device__ __forceinline__ void wait_flags2(volatile unsigned* fa, int na,
                                            volatile unsigned* fb, int nb,
                                            unsigned tgt, int tid) {
    if (tid < na) { while (fa[tid] < tgt) { } }
    else if (tid < na + nb) { while (fb[tid - na] < tgt) { } }
    __syncthreads();
    if (tid == 0) __threadfence();
    __syncthreads();
}
// producer: one release store into OWN slot (no atomic serialization)
__device__ __forceinline__ void signal_flag(volatile unsigned* slot, unsigned val, int tid) {
    __syncthreads();
    if (tid == 0) { __threadfence(); *slot = val; }
}

// ---------------- mega prologue ----------------
#define N4_ENC   2097152
#define N4_WATTN 65536
#define N4_WIH0  393216
#define N4_WIH1  196608
#define N4_WHH0  196608
#define N4_WHH1  196608
#define N4_WOUT  8192000
#define N4_TOTAL (N4_ENC + N4_WATTN + N4_WIH0 + N4_WIH1 + N4_WHH0 + N4_WHH1 + N4_WOUT)

__global__ void mega_prologue(const float* __restrict__ enc, const float* __restrict__ wat,
                              const float* __restrict__ wi0, const float* __restrict__ wi1,
                              const float* __restrict__ wh0, const float* __restrict__ wh1,
                              const float* __restrict__ wo,
                              const int* __restrict__ din, const float* __restrict__ table)
{
    long long i = (long long)blockIdx.x * 256 + threadIdx.x;

    if (i < BH) {
        g_h0buf[i] = 0.0f; g_h1buf[i] = 0.0f;
        g_h0h[i] = __float2half(0.0f); g_h1h[i] = __float2half(0.0f);
    }
    if (i < 64) {
        g_fattn[i] = 0;
        if (i < 32) { g_fgh0[i] = 0; g_fgh1[i] = 0; g_fg0[i] = 0; g_fg1[i] = 0; }
    }

    if (i < Un * Bn * Hn) {
        int h = (int)i & (Hn - 1);
        int m = (int)(i >> 9);
        int u = m >> 5, b = m & 31;
        float v = table[(size_t)din[b * Un + u] * Hn + h];
        g_embQ[i] = v;
        g_embH[i] = __float2half(v);
    }

    if (i < N4_TOTAL) {
        const float* src; __half* dst; long long off = i;
        if (off < N4_ENC)                 { src = enc; dst = g_enc_h; }
        else if ((off -= N4_ENC)   < N4_WATTN) { src = wat; dst = g_Wattn_h; }
        else if ((off -= N4_WATTN) < N4_WIH0)  { src = wi0; dst = g_Wih0_h; }
        else if ((off -= N4_WIH0)  < N4_WIH1)  { src = wi1; dst = g_Wih1_h; }
        else if ((off -= N4_WIH1)  < N4_WHH0)  { src = wh0; dst = g_Whh0_h; }
        else if ((off -= N4_WHH0)  < N4_WHH1)  { src = wh1; dst = g_Whh1_h; }
        else { off -= N4_WHH1; src = wo; dst = g_Wout_h; }
        float4 v = reinterpret_cast<const float4*>(src)[off];
        reinterpret_cast<__half2*>(dst)[2 * off]     = __floats2half2_rn(v.x, v.y);
        reinterpret_cast<__half2*>(dst)[2 * off + 1] = __floats2half2_rn(v.z, v.w);
    }
}

// ---------------- pipelined fp16 GEMM with ldmatrix ----------------
#define SROW 72
__global__ __launch_bounds__(256) void gemm_h16(
    const __half* __restrict__ A, const __half* __restrict__ Bw, int ldb,
    const float* __restrict__ bias, void* __restrict__ Cout,
    int M, int N, int K, int mode, int swap)
{
    extern __shared__ __align__(16) __half gsm[];
    __half* sA = gsm;
    __half* sB = gsm + 2 * 128 * SROW;

    int tid = threadIdx.x, lane = tid & 31, warp = tid >> 5;
    int wm = (warp >> 1) * 32;
    int wn = (warp & 1) * 64;
    int bm = (swap ? blockIdx.x : blockIdx.y) * 128;
    int bn = (swap ? blockIdx.y : blockIdx.x) * 128;
    int r = lane >> 2, c = (lane & 3) * 2;

    unsigned sA_u = (unsigned)__cvta_generic_to_shared(sA);
    unsigned sB_u = (unsigned)__cvta_generic_to_shared(sB);

    int ri = lane & 7, g = lane >> 3;
    unsigned laneA = (unsigned)(((ri + (g & 1) * 8) * SROW + (g >> 1) * 8) * 2);
    unsigned laneB = (unsigned)(((ri + (g >> 1) * 8) * SROW + (g & 1) * 8) * 2);

    int ldrow = tid >> 3, ldseg = (tid & 7) * 8;

    float acc[2][8][4];
#pragma unroll
    for (int mi = 0; mi < 2; mi++)
#pragma unroll
        for (int ni = 0; ni < 8; ni++)
#pragma unroll
            for (int q = 0; q < 4; q++) acc[mi][ni][q] = 0.0f;

    int nk = K >> 6;

#pragma unroll
    for (int i = 0; i < 4; i++) {
        int row = ldrow + i * 32;
        cp_async16(sA_u + (unsigned)((row * SROW + ldseg) * 2),
                   A + (size_t)(bm + row) * K + ldseg);
        cp_async16(sB_u + (unsigned)((row * SROW + ldseg) * 2),
                   Bw + (size_t)(bn + row) * ldb + ldseg);
    }
    asm volatile("cp.async.commit_group;");

    for (int ki = 0; ki < nk; ki++) {
        asm volatile("cp.async.wait_group 0;");
        __syncthreads();
        if (ki + 1 < nk) {
            int kt = (ki + 1) << 6;
            unsigned stoff = (unsigned)(((ki + 1) & 1) * 128 * SROW * 2);
#pragma unroll
            for (int i = 0; i < 4; i++) {
                int row = ldrow + i * 32;
                cp_async16(sA_u + stoff + (unsigned)((row * SROW + ldseg) * 2),
                           A + (size_t)(bm + row) * K + kt + ldseg);
                cp_async16(sB_u + stoff + (unsigned)((row * SROW + ldseg) * 2),
                           Bw + (size_t)(bn + row) * ldb + kt + ldseg);
            }
            asm volatile("cp.async.commit_group;");
        }
        unsigned cA_u = sA_u + (unsigned)((ki & 1) * 128 * SROW * 2);
        unsigned cB_u = sB_u + (unsigned)((ki & 1) * 128 * SROW * 2);
#pragma unroll
        for (int ks = 0; ks < 4; ks++) {
            int k0 = ks * 16;
            unsigned a[2][4], bf[8][2];
#pragma unroll
            for (int mi = 0; mi < 2; mi++) {
                unsigned addr = cA_u + (unsigned)(((wm + mi * 16) * SROW + k0) * 2) + laneA;
                LDSM4(a[mi][0], a[mi][1], a[mi][2], a[mi][3], addr);
            }
#pragma unroll
            for (int nj = 0; nj < 4; nj++) {
                unsigned addr = cB_u + (unsigned)(((wn + nj * 16) * SROW + k0) * 2) + laneB;
                LDSM4(bf[2 * nj][0], bf[2 * nj][1], bf[2 * nj + 1][0], bf[2 * nj + 1][1], addr);
            }
#pragma unroll
            for (int mi = 0; mi < 2; mi++)
#pragma unroll
                for (int ni = 0; ni < 8; ni++)
                    hmma(acc[mi][ni], a[mi][0], a[mi][1], a[mi][2], a[mi][3],
                         bf[ni][0], bf[ni][1]);
        }
        __syncthreads();
    }

#pragma unroll
    for (int mi = 0; mi < 2; mi++)
#pragma unroll
        for (int ni = 0; ni < 8; ni++)
#pragma unroll
            for (int h = 0; h < 2; h++) {
                int m = bm + wm + mi * 16 + r + h * 8;
                int n = bn + wn + ni * 8 + c;
                float v0 = acc[mi][ni][h * 2], v1 = acc[mi][ni][h * 2 + 1];
                if (mode == 0) {
                    *(__half2*)&reinterpret_cast<__half*>(Cout)[(size_t)m * N + n] =
                        __floats2half2_rn(v0, v1);
                } else if (mode == 1) {
                    *(float2*)&reinterpret_cast<float*>(Cout)[(size_t)m * N + n] =
                        make_float2(v0 + bias[n], v1 + bias[n + 1]);
                } else {
                    int b = m & 31, u = m >> 5;
                    *(float2*)&reinterpret_cast<float*>(Cout)
                        [(size_t)b * Un * Vn + (size_t)u * Vn + n] =
                        make_float2(v0 + bias[n], v1 + bias[n + 1]);
                }
            }
}

// ---------------- persistent-kernel helpers ----------------
__device__ __forceinline__ void stage_x(__half* sX, const __half* __restrict__ src,
                                        int stride, int tid)
{
#pragma unroll
    for (int it = 0; it < 8; it++) {
        int i = tid + it * 256;
        int sr = i >> 6;
        int j = i & 63;
        int cc = j >> 4, sg = (j & 15) * 8;
        *(uint4*)(sX + cc * 4352 + sr * 136 + sg) =
            *(const uint4*)(src + (size_t)sr * stride + cc * 128 + sg);
    }
}

__device__ __forceinline__ void mma_slab(const __half* sW, const __half* sX,
                                         float acc[4][4], int warp, int lane)
{
    int m = lane >> 2, kq = (lane & 3) * 2;
#pragma unroll
    for (int cc = 0; cc < 4; cc++) {
        const __half* wc = sW + cc * 6528;
        const __half* xc = sX + cc * 4352;
#pragma unroll
        for (int ks = 0; ks < 8; ks++) {
            int k0 = ks * 16;
            unsigned a0 = *(unsigned*)(wc + (warp * 16 + m) * 136 + k0 + kq);
            unsigned a1 = *(unsigned*)(wc + (warp * 16 + m + 8) * 136 + k0 + kq);
            unsigned a2 = *(unsigned*)(wc + (warp * 16 + m) * 136 + k0 + kq + 8);
            unsigned a3 = *(unsigned*)(wc + (warp * 16 + m + 8) * 136 + k0 + kq + 8);
#pragma unroll
            for (int nt = 0; nt < 4; nt++) {
                unsigned b0 = *(unsigned*)(xc + (nt * 8 + m) * 136 + k0 + kq);
                unsigned b1 = *(unsigned*)(xc + (nt * 8 + m) * 136 + k0 + kq + 8);
                hmma(acc[nt], a0, a1, a2, a3, b0, b1);
            }
        }
    }
}

// ---------------- persistent decode loop ----------------
__global__ __launch_bounds__(256, 1) void decode_persistent(
    const int* __restrict__ lens,
    const float* __restrict__ b_hh0, const float* __restrict__ b_ih1,
    const float* __restrict__ b_hh1)
{
    extern __shared__ __align__(16) char dynsm[];
    __half* sW = (__half*)dynsm;
    __half* sX = (__half*)(dynsm + SMEM_W_BYTES);
    char* scr = dynsm + SMEM_W_BYTES + SMEM_X_BYTES;

    int bid = blockIdx.x, tid = threadIdx.x;
    int warp = tid >> 5, lane = tid & 31;

    {
        const __half* Wsrc; int ld, coff, triplet, base;
        if (bid < 32)      { Wsrc = g_Wih0_h; ld = HEn; coff = Hn; triplet = 1; base = bid * 16; }
        else if (bid < 64) { Wsrc = g_Wih1_h; ld = Hn;  coff = 0;  triplet = 1; base = (bid - 32) * 16; }
        else if (bid < 96) { Wsrc = g_Whh0_h; ld = Hn;  coff = 0;  triplet = 0; base = (bid - 64) * 48; }
        else               { Wsrc = g_Whh1_h; ld = Hn;  coff = 0;  triplet = 0; base = (bid - 96) * 48; }
#pragma unroll
        for (int cc = 0; cc < 4; cc++) {
            for (int i = tid; i < 768; i += 256) {
                int sr = i >> 4, sg = (i & 15) * 8;
                int grow = triplet ? ((sr >> 4) * 512 + base + (sr & 15)) : (base + sr);
                *(uint4*)(sW + cc * 6528 + sr * 136 + sg) =
                    *(const uint4*)(Wsrc + (size_t)grow * ld + coff + cc * 128 + sg);
            }
        }
        __syncthreads();
    }

    int mylen = (bid < 64) ? lens[bid >> 1] : 0;

    for (int u = 0; u < Un; u++) {
        const float*  h0old  = g_h0buf + (u & 1) * BH;
        float*        h0new  = g_h0buf + ((u + 1) & 1) * BH;
        const float*  h1old  = g_h1buf + (u & 1) * BH;
        float*        h1new  = g_h1buf + ((u + 1) & 1) * BH;
        const __half* h0oldh = g_h0h + (u & 1) * BH;
        __half*       h0newh = g_h0h + ((u + 1) & 1) * BH;
        const __half* h1oldh = g_h1h + (u & 1) * BH;
        __half*       h1newh = g_h1h + ((u + 1) & 1) * BH;
        __half*       acts_u = g_acts + (size_t)u * Bn * HEn;

        if (bid < 64) {
            // ===== fused attention =====
            wait_flags(g_fg1, 32, (unsigned)u, tid);
            int b = bid >> 1;
            int eoff = (bid & 1) * 256;
            float* qs = (float*)scr;
            float* p  = qs + 512;
            float* red = p + 512;
            const float* q = (u == 0) ? (g_embQ + b * Hn) : (h1old + b * Hn);
            for (int i = tid; i < Hn; i += 256) qs[i] = q[i];
            __syncthreads();

            float sc0, sc1;
            {
                const uint4* r0 = (const uint4*)(g_encproj_h + ((size_t)b * Tn + tid) * Hn);
                const uint4* r1 = (const uint4*)(g_encproj_h + ((size_t)b * Tn + tid + 256) * Hn);
                float a00 = 0.f, a01 = 0.f, a10 = 0.f, a11 = 0.f;
#pragma unroll
                for (int ib = 0; ib < 8; ib++) {
                    uint4 v0[8], v1[8];
#pragma unroll
                    for (int j = 0; j < 8; j++) { v0[j] = r0[ib * 8 + j]; v1[j] = r1[ib * 8 + j]; }
#pragma unroll
                    for (int j = 0; j < 8; j++) {
                        int i = ib * 8 + j;
                        const __half2* h0p = (const __half2*)&v0[j];
                        const __half2* h1p = (const __half2*)&v1[j];
                        const float* qq = qs + i * 8;
                        float2 f;
                        f = __half22float2(h0p[0]); a00 += f.x * qq[0] + f.y * qq[1];
                        f = __half22float2(h0p[1]); a01 += f.x * qq[2] + f.y * qq[3];
                        f = __half22float2(h0p[2]); a00 += f.x * qq[4] + f.y * qq[5];
                        f = __half22float2(h0p[3]); a01 += f.x * qq[6] + f.y * qq[7];
                        f = __half22float2(h1p[0]); a10 += f.x * qq[0] + f.y * qq[1];
                        f = __half22float2(h1p[1]); a11 += f.x * qq[2] + f.y * qq[3];
                        f = __half22float2(h1p[2]); a10 += f.x * qq[4] + f.y * qq[5];
                        f = __half22float2(h1p[3]); a11 += f.x * qq[6] + f.y * qq[7];
                    }
                }
                sc0 = (tid < mylen) ? (a00 + a01) : -INFINITY;
                sc1 = (tid + 256 < mylen) ? (a10 + a11) : -INFINITY;
            }
            float wm_ = fmaxf(sc0, sc1);
#pragma unroll
            for (int off = 16; off > 0; off >>= 1)
                wm_ = fmaxf(wm_, __shfl_xor_sync(0xFFFFFFFFu, wm_, off));
            if (lane == 0) red[warp] = wm_;
            __syncthreads();
            float mx = fmaxf(fmaxf(fmaxf(red[0], red[1]), fmaxf(red[2], red[3])),
                             fmaxf(fmaxf(red[4], red[5]), fmaxf(red[6], red[7])));
            float e0 = expf(sc0 - mx), e1 = expf(sc1 - mx);
            p[tid] = e0; p[tid + 256] = e1;
            float ws = e0 + e1;
#pragma unroll
            for (int off = 16; off > 0; off >>= 1)
                ws += __shfl_xor_sync(0xFFFFFFFFu, ws, off);
            if (lane == 0) red[warp] = ws;
            __syncthreads();
            float inv = 1.0f / (red[0] + red[1] + red[2] + red[3]
                              + red[4] + red[5] + red[6] + red[7]);

            int slot = tid & 31, tg = tid >> 5;
            const __half* encb = g_enc_h + (size_t)b * Tn * En + eoff + slot * 8;
            float cx[8];
#pragma unroll
            for (int j = 0; j < 8; j++) cx[j] = 0.0f;
#pragma unroll
            for (int ob = 0; ob < 8; ob++) {
                uint4 v[8];
#pragma unroll
                for (int j = 0; j < 8; j++) {
                    int t = (ob * 8 + j) * 8 + tg;
                    v[j] = *(const uint4*)(encb + (size_t)t * En);
                }
#pragma unroll
                for (int j = 0; j < 8; j++) {
                    int t = (ob * 8 + j) * 8 + tg;
                    const __half2* hp = (const __half2*)&v[j];
                    float w = p[t];
                    float2 f;
                    f = __half22float2(hp[0]); cx[0] += w * f.x; cx[1] += w * f.y;
                    f = __half22float2(hp[1]); cx[2] += w * f.x; cx[3] += w * f.y;
                    f = __half22float2(hp[2]); cx[4] += w * f.x; cx[5] += w * f.y;
                    f = __half22float2(hp[3]); cx[6] += w * f.x; cx[7] += w * f.y;
                }
            }
            float* part = (float*)sX;
            *(float4*)(part + tid * 8)     = make_float4(cx[0], cx[1], cx[2], cx[3]);
            *(float4*)(part + tid * 8 + 4) = make_float4(cx[4], cx[5], cx[6], cx[7]);
            __syncthreads();
            {
                int sl = tid >> 3, j = tid & 7;
                float s = 0.f;
#pragma unroll
                for (int t2 = 0; t2 < 8; t2++) s += part[((t2 << 5) + sl) * 8 + j];
                acts_u[(size_t)b * HEn + Hn + eoff + tid] = __float2half(s * inv);
            }
            signal_flag(&g_fattn[bid], (unsigned)(u + 1), tid);
        } else if (bid < 96) {
            wait_flags(g_fg0, 32, (unsigned)u, tid);
            stage_x(sX, h0oldh, Hn, tid);
            __syncthreads();
            float acc[4][4];
#pragma unroll
            for (int nt = 0; nt < 4; nt++)
#pragma unroll
                for (int q = 0; q < 4; q++) acc[nt][q] = 0.0f;
            if (warp < 3) {
                mma_slab(sW, sX, acc, warp, lane);
                int m = lane >> 2, nq = (lane & 3) * 2;
                int r0 = (bid - 64) * 48 + warp * 16 + m;
#pragma unroll
                for (int nt = 0; nt < 4; nt++) {
                    int n = nt * 8 + nq;
                    g_gh0[(size_t)n * G3H + r0]           = acc[nt][0];
                    g_gh0[(size_t)(n + 1) * G3H + r0]     = acc[nt][1];
                    g_gh0[(size_t)n * G3H + r0 + 8]       = acc[nt][2];
                    g_gh0[(size_t)(n + 1) * G3H + r0 + 8] = acc[nt][3];
                }
            }
            signal_flag(&g_fgh0[bid - 64], (unsigned)(u + 1), tid);
        } else {
            wait_flags(g_fg1, 32, (unsigned)u, tid);
            stage_x(sX, h1oldh, Hn, tid);
            __syncthreads();
            float acc[4][4];
#pragma unroll
            for (int nt = 0; nt < 4; nt++)
#pragma unroll
                for (int q = 0; q < 4; q++) acc[nt][q] = 0.0f;
            if (warp < 3) {
                mma_slab(sW, sX, acc, warp, lane);
                int m = lane >> 2, nq = (lane & 3) * 2;
                int r0 = (bid - 96) * 48 + warp * 16 + m;
#pragma unroll
                for (int nt = 0; nt < 4; nt++) {
                    int n = nt * 8 + nq;
                    g_gh1[(size_t)n * G3H + r0]           = acc[nt][0];
                    g_gh1[(size_t)(n + 1) * G3H + r0]     = acc[nt][1];
                    g_gh1[(size_t)n * G3H + r0 + 8]       = acc[nt][2];
                    g_gh1[(size_t)(n + 1) * G3H + r0 + 8] = acc[nt][3];
                }
            }
            signal_flag(&g_fgh1[bid - 96], (unsigned)(u + 1), tid);
        }

        if (bid < 32) {
            wait_flags2(g_fattn, 64, g_fgh0, 32, (unsigned)(u + 1), tid);
            int ibase = bid * 16;
            stage_x(sX, acts_u + Hn, HEn, tid);
            __syncthreads();
            float acc[4][4];
#pragma unroll
            for (int nt = 0; nt < 4; nt++)
#pragma unroll
                for (int q = 0; q < 4; q++) acc[nt][q] = 0.0f;
            float* gout = (float*)scr;
            if (warp < 3) {
                mma_slab(sW, sX, acc, warp, lane);
                int m = lane >> 2, nq = (lane & 3) * 2;
#pragma unroll
                for (int nt = 0; nt < 4; nt++) {
                    int n = nt * 8 + nq;
                    gout[warp * 528 + m * 33 + n]           = acc[nt][0];
                    gout[warp * 528 + m * 33 + n + 1]       = acc[nt][1];
                    gout[warp * 528 + (m + 8) * 33 + n]     = acc[nt][2];
                    gout[warp * 528 + (m + 8) * 33 + n + 1] = acc[nt][3];
                }
            }
            __syncthreads();
            const float* pre = g_gi0pre + (size_t)u * Bn * G3H;
#pragma unroll
            for (int it = 0; it < 2; it++) {
                int idx = tid + it * 256;
                int il = idx & 15, b = idx >> 4;
                int i = ibase + il;
                const float* pb = pre + (size_t)b * G3H;
                float gir = pb[i]        + gout[il * 33 + b];
                float giz = pb[512 + i]  + gout[528 + il * 33 + b];
                float gin = pb[1024 + i] + gout[1056 + il * 33 + b];
                const float* gb = g_gh0 + (size_t)b * G3H;
                float r = sigmoidf_(gir + gb[i] + b_hh0[i]);
                float z = sigmoidf_(giz + gb[512 + i] + b_hh0[512 + i]);
                float n = tanhf(gin + r * (gb[1024 + i] + b_hh0[1024 + i]));
                float hv = (1.0f - z) * n + z * h0old[b * Hn + i];
                h0new[b * Hn + i] = hv;
                h0newh[b * Hn + i] = __float2half(hv);
            }
            signal_flag(&g_fg0[bid], (unsigned)(u + 1), tid);
        }

        if (bid >= 32 && bid < 64) {
            wait_flags2(g_fg0, 32, g_fgh1, 32, (unsigned)(u + 1), tid);
            int ibase = (bid - 32) * 16;
            stage_x(sX, h0newh, Hn, tid);
            __syncthreads();
            float acc[4][4];
#pragma unroll
            for (int nt = 0; nt < 4; nt++)
#pragma unroll
                for (int q = 0; q < 4; q++) acc[nt][q] = 0.0f;
            float* gout = (float*)scr;
            if (warp < 3) {
                mma_slab(sW, sX, acc, warp, lane);
                int m = lane >> 2, nq = (lane & 3) * 2;
#pragma unroll
                for (int nt = 0; nt < 4; nt++) {
                    int n = nt * 8 + nq;
                    gout[warp * 528 + m * 33 + n]           = acc[nt][0];
                    gout[warp * 528 + m * 33 + n + 1]       = acc[nt][1];
                    gout[warp * 528 + (m + 8) * 33 + n]     = acc[nt][2];
                    gout[warp * 528 + (m + 8) * 33 + n + 1] = acc[nt][3];
                }
            }
            __syncthreads();
#pragma unroll
            for (int it = 0; it < 2; it++) {
                int idx = tid + it * 256;
                int il = idx & 15, b = idx >> 4;
                int i = ibase + il;
                float gir = b_ih1[i]        + gout[il * 33 + b];
                float giz = b_ih1[512 + i]  + gout[528 + il * 33 + b];
                float gin = b_ih1[1024 + i] + gout[1056 + il * 33 + b];
                const float* gb = g_gh1 + (size_t)b * G3H;
                float r = sigmoidf_(gir + gb[i] + b_hh1[i]);
                float z = sigmoidf_(giz + gb[512 + i] + b_hh1[512 + i]);
                float n = tanhf(gin + r * (gb[1024 + i] + b_hh1[1024 + i]));
                float hv = (1.0f - z) * n + z * h1old[b * Hn + i];
                h1new[b * Hn + i] = hv;
                __half hh = __float2half(hv);
                h1newh[b * Hn + i] = hh;
                acts_u[(size_t)b * HEn + i] = hh;
            }
            signal_flag(&g_fg1[bid - 32], (unsigned)(u + 1), tid);
        }
    }
}

// ---------------- launch ----------------
extern "C" void kernel_launch(void* const* d_in, const int* in_sizes, int n_in,
                              void* d_out, int out_size)
{
    const float* encoder_out = (const float*)d_in[0];
    const int*   lens        = (const int*)d_in[1];
    const int*   din         = (const int*)d_in[2];
    const float* emb_table   = (const float*)d_in[3];
    const float* W_attn      = (const float*)d_in[4];
    const float* W_ih0       = (const float*)d_in[5];
    const float* W_hh0       = (const float*)d_in[6];
    const float* b_ih0       = (const float*)d_in[7];
    const float* b_hh0       = (const float*)d_in[8];
    const float* W_ih1       = (const float*)d_in[9];
    const float* W_hh1       = (const float*)d_in[10];
    const float* b_ih1       = (const float*)d_in[11];
    const float* b_hh1       = (const float*)d_in[12];
    const float* W_out       = (const float*)d_in[13];
    const float* b_out       = (const float*)d_in[14];
    float* out = (float*)d_out;

    __half *enc_h, *encproj_h, *Wattn_h, *Wih0_h, *embH, *acts, *Wout_h;
    float *gi0pre;
    cudaGetSymbolAddress((void**)&enc_h, g_enc_h);
    cudaGetSymbolAddress((void**)&encproj_h, g_encproj_h);
    cudaGetSymbolAddress((void**)&Wattn_h, g_Wattn_h);
    cudaGetSymbolAddress((void**)&Wih0_h, g_Wih0_h);
    cudaGetSymbolAddress((void**)&embH, g_embH);
    cudaGetSymbolAddress((void**)&acts, g_acts);
    cudaGetSymbolAddress((void**)&Wout_h, g_Wout_h);
    cudaGetSymbolAddress((void**)&gi0pre, g_gi0pre);

    static int smem_set = 0;
    if (!smem_set) {
        cudaFuncSetAttribute(decode_persistent,
                             cudaFuncAttributeMaxDynamicSharedMemorySize, SMEM_TOTAL_B);
        cudaFuncSetAttribute(gemm_h16,
                             cudaFuncAttributeMaxDynamicSharedMemorySize, GEMM_SMEM_B);
        smem_set = 1;
    }

    mega_prologue<<<(N4_TOTAL + 255) / 256, 256>>>(
        encoder_out, W_attn, W_ih0, W_ih1, W_hh0, W_hh1, W_out, din, emb_table);
    gemm_h16<<<dim3(Hn / 128, (Bn * Tn) / 128), 256, GEMM_SMEM_B>>>(
        enc_h, Wattn_h, En, nullptr, encproj_h, Bn * Tn, Hn, En, 0, 0);
    gemm_h16<<<dim3(G3H / 128, (Un * Bn) / 128), 256, GEMM_SMEM_B>>>(
        embH, Wih0_h, HEn, b_ih0, gi0pre, Un * Bn, G3H, Hn, 1, 0);
    decode_persistent<<<NB, 256, SMEM_TOTAL_B>>>(lens, b_hh0, b_ih1, b_hh1);
    gemm_h16<<<dim3((Un * Bn) / 128, Vn / 128), 256, GEMM_SMEM_B>>>(
        acts, Wout_h, HEn, b_out, out, Un * Bn, Vn, HEn, 2, 1);
}